// round 3
// baseline (speedup 1.0000x reference)
#include <cuda_runtime.h>
#include <math.h>

#define B_ 8
#define N_ 2048
#define F_ 256
#define K_ 205
#define ACAP 256
#define CSRCAP 128
#define SROWCAP 130
#define ROWS_ (B_*N_)

// ---- static scratch (no runtime allocation allowed) ----
__device__ float g_t[ROWS_];
__device__ float g_radj[ROWS_];
__device__ float g_adiag[ROWS_];
__device__ float g_dg[ROWS_];
__device__ float g_alpha[ROWS_];
__device__ int   g_ccol[ROWS_*CSRCAP];
__device__ float g_cval[ROWS_*CSRCAP];
__device__ int   g_ccnt[ROWS_];
__device__ int   g_sj[ROWS_*SROWCAP];
__device__ float g_sv[ROWS_*SROWCAP];
__device__ int   g_scnt[ROWS_];
__device__ int   g_colid[B_*ACAP];
__device__ float g_w[B_*ACAP];
__device__ int   g_acnt[B_];
__device__ int   g_rank[ROWS_];
__device__ float g_T[(size_t)ROWS_*ACAP];

// ---- K1: row sums + CSR of adj (one warp per row, order-preserving compaction) ----
__global__ void k_csr(const float* __restrict__ adj){
    int row = blockIdx.x * 8 + (threadIdx.x >> 5);
    if (row >= ROWS_) return;
    int lane = threadIdx.x & 31;
    int n = row % N_;
    const float* ar = adj + (size_t)row * N_;
    float sum = 0.f, diag = 0.f;
    int cnt = 0, base = row * CSRCAP;
    for (int c = 0; c < N_; c += 32) {
        int m = c + lane;
        float a = ar[m];
        sum += a;
        if (m == n) diag = a;
        unsigned msk = __ballot_sync(0xffffffffu, a != 0.f);
        if (a != 0.f) {
            int pos = cnt + __popc(msk & ((1u << lane) - 1u));
            if (pos < CSRCAP) { g_ccol[base + pos] = m; g_cval[base + pos] = a; }
        }
        cnt += __popc(msk);
    }
    for (int o = 16; o; o >>= 1) {
        sum  += __shfl_xor_sync(0xffffffffu, sum,  o);
        diag += __shfl_xor_sync(0xffffffffu, diag, o);
    }
    if (lane == 0) {
        g_radj[row] = sum;
        g_adiag[row] = diag;
        g_ccnt[row] = cnt < CSRCAP ? cnt : CSRCAP;
    }
}

// ---- K2: t = x @ W (warp per row) ----
__global__ void k_t(const float* __restrict__ x, const float* __restrict__ W){
    int row = blockIdx.x * 8 + (threadIdx.x >> 5);
    if (row >= ROWS_) return;
    int lane = threadIdx.x & 31;
    const float* xr = x + (size_t)row * F_;
    float s = 0.f;
    #pragma unroll
    for (int f = lane; f < F_; f += 32) s += xr[f] * W[f];
    for (int o = 16; o; o >>= 1) s += __shfl_xor_sync(0xffffffffu, s, o);
    if (lane == 0) g_t[row] = s;
}

// ---- K3: dg = (rowsum(A_hat))^-0.5 ; clip(.,1) is a no-op since rowsum>=1 ----
__global__ void k_dg(){
    int i = blockIdx.x * blockDim.x + threadIdx.x;
    if (i < ROWS_) g_dg[i] = rsqrtf(g_radj[i] + 1.f);
}

// ---- K4: alpha = sigmoid((dg_n * sum_m A_hat[n,m] dg_m t_m + b)^2) ----
__global__ void k_alpha(const float* __restrict__ bptr){
    int row = blockIdx.x * 8 + (threadIdx.x >> 5);
    if (row >= ROWS_) return;
    int lane = threadIdx.x & 31;
    int b = row / N_;
    int base = row * CSRCAP;
    int cnt = g_ccnt[row];
    float s = 0.f;
    for (int e = lane; e < cnt; e += 32) {
        int m = g_ccol[base + e];
        s += g_cval[base + e] * g_dg[b * N_ + m] * g_t[b * N_ + m];
    }
    for (int o = 16; o; o >>= 1) s += __shfl_xor_sync(0xffffffffu, s, o);
    if (lane == 0) {
        s += g_dg[row] * g_t[row];            // identity part of A_hat
        float pre = g_dg[row] * s + bptr[0];
        float z = pre * pre;
        g_alpha[row] = 1.f / (1.f + expf(-z));
    }
}

// ---- K5: per-batch top-K via bitonic sort of 2048 (value desc, index asc) ----
__global__ void k_topk(float* __restrict__ out_ti){
    int b = blockIdx.x;
    int tid = threadIdx.x;
    __shared__ unsigned long long sk[N_];
    __shared__ float cutv;
    __shared__ int acnt;
    for (int i = tid; i < N_; i += 1024) {
        g_rank[b * N_ + i] = -1;
        float v = g_alpha[b * N_ + i];
        unsigned u = __float_as_uint(v);
        u = (u & 0x80000000u) ? ~u : (u | 0x80000000u);   // orderable
        sk[i] = ((unsigned long long)(~u) << 32) | (unsigned)i; // asc key = desc value
    }
    __syncthreads();
    for (int k = 2; k <= N_; k <<= 1) {
        for (int j = k >> 1; j > 0; j >>= 1) {
            for (int t = tid; t < N_; t += 1024) {
                int ixj = t ^ j;
                if (ixj > t) {
                    bool up = ((t & k) == 0);
                    unsigned long long a = sk[t], c = sk[ixj];
                    if ((a > c) == up) { sk[t] = c; sk[ixj] = a; }
                }
            }
            __syncthreads();
        }
    }
    if (tid == 0) {
        int idxK = (int)(sk[K_ - 1] & 0xffffffffu);
        cutv = g_alpha[b * N_ + idxK];
        int A = K_;
        while (A < ACAP) {      // near-ties within 1e-7 below cut also get weight
            int id = (int)(sk[A] & 0xffffffffu);
            float v = g_alpha[b * N_ + id];
            if (v + 1e-7f - cutv > 0.f) A++; else break;
        }
        acnt = A;
        g_acnt[b] = A;
    }
    __syncthreads();
    for (int j = tid; j < acnt; j += 1024) {
        int id = (int)(sk[j] & 0xffffffffu);
        g_colid[b * ACAP + j] = id;
        g_w[b * ACAP + j] = g_alpha[b * N_ + id] + 1e-7f - cutv;
        g_rank[b * N_ + id] = j;
    }
    for (int j = tid; j < K_; j += 1024) {
        int id = (int)(sk[j] & 0xffffffffu);
        out_ti[b * K_ + j] = (float)id;
    }
}

// ---- K6: build normalized S rows (sparse list + dense scatter) ----
__global__ void k_sbuild(float* __restrict__ S_out){
    int row = blockIdx.x * 8 + (threadIdx.x >> 5);
    if (row >= ROWS_) return;
    int lane = threadIdx.x & 31;
    int b = row / N_, n = row % N_;
    if (g_radj[row] <= 0.f) {                 // mask = (adj.sum(-1) > 0)
        if (lane == 0) g_scnt[row] = 0;
        return;
    }
    float dgn = g_dg[row];
    int cnt = g_ccnt[row], base = row * CSRCAP;
    bool hasdiag = (g_adiag[row] != 0.f);
    // pass 1: row sum of unnormalized S
    float rs = 0.f;
    for (int e = lane; e < cnt; e += 32) {
        int m = g_ccol[base + e];
        int j = g_rank[b * N_ + m];
        if (j >= 0) {
            float ahat = g_cval[base + e] + (m == n ? 1.f : 0.f);
            rs += dgn * ahat * g_dg[b * N_ + m] * g_w[b * ACAP + j];
        }
    }
    if (!hasdiag && lane == 0) {
        int j = g_rank[row];
        if (j >= 0) rs += dgn * dgn * g_w[b * ACAP + j];
    }
    for (int o = 16; o; o >>= 1) rs += __shfl_xor_sync(0xffffffffu, rs, o);
    float inv = 1.f / fmaxf(rs, 1e-12f);
    // pass 2: write normalized values (order-preserving)
    int sc = 0, sbase = row * SROWCAP;
    for (int c = 0; c < cnt; c += 32) {
        int e = c + lane;
        bool act = false; int j = -1, m = -1; float v = 0.f;
        if (e < cnt) {
            m = g_ccol[base + e];
            j = g_rank[b * N_ + m];
            if (j >= 0) {
                act = true;
                float ahat = g_cval[base + e] + (m == n ? 1.f : 0.f);
                v = dgn * ahat * g_dg[b * N_ + m] * g_w[b * ACAP + j] * inv;
            }
        }
        unsigned msk = __ballot_sync(0xffffffffu, act);
        if (act) {
            int pos = sc + __popc(msk & ((1u << lane) - 1u));
            if (pos < SROWCAP) { g_sj[sbase + pos] = j; g_sv[sbase + pos] = v; }
            S_out[(size_t)row * N_ + m] = v;
        }
        sc += __popc(msk);
    }
    if (!hasdiag) {
        int add = 0;
        if (lane == 0) {
            int j = g_rank[row];
            if (j >= 0) {
                float v = dgn * dgn * g_w[b * ACAP + j] * inv;
                if (sc < SROWCAP) { g_sj[sbase + sc] = j; g_sv[sbase + sc] = v; }
                S_out[(size_t)row * N_ + n] = v;
                add = 1;
            }
        }
        sc += __shfl_sync(0xffffffffu, add, 0);
    }
    if (lane == 0) g_scnt[row] = sc < SROWCAP ? sc : SROWCAP;
}

// ---- K7: T[n,:] = sum_k adj[n,k] * Srow[k]  (block per row, smem accumulators) ----
__global__ void k_T(){
    int row = blockIdx.x;
    int b = row / N_;
    int tid = threadIdx.x;
    __shared__ float acc[ACAP];
    for (int i = tid; i < ACAP; i += 128) acc[i] = 0.f;
    __syncthreads();
    int cnt = g_ccnt[row], base = row * CSRCAP;
    for (int e = tid; e < cnt; e += 128) {
        int k = g_ccol[base + e];
        float a = g_cval[base + e];
        size_t krow = (size_t)b * N_ + k;
        int sb = (int)krow * SROWCAP;
        int sc = g_scnt[krow];
        for (int q = 0; q < sc; q++)
            atomicAdd(&acc[g_sj[sb + q]], a * g_sv[sb + q]);
    }
    __syncthreads();
    int A = g_acnt[b];
    float* Trow = g_T + (size_t)row * ACAP;
    for (int j = tid; j < A; j += 128) Trow[j] = acc[j];
}

// ---- K8: coarse active block = Scol_m^T . T, then floor quantize ----
__global__ void k_coarse(const float* __restrict__ S_out, float* __restrict__ out_co){
    int b = blockIdx.y;
    int jm = blockIdx.x;
    int A = g_acnt[b];
    if (jm >= A) return;
    int tid = threadIdx.x;
    int m = g_colid[b * ACAP + jm];
    size_t mrow = (size_t)b * N_ + m;
    __shared__ int   sn[CSRCAP + 1];
    __shared__ float sv[CSRCAP + 1];
    int cnt = g_ccnt[mrow], base = (int)mrow * CSRCAP;
    if (tid < cnt) {
        int n2 = g_ccol[base + tid];
        sn[tid] = n2;
        sv[tid] = S_out[((size_t)b * N_ + n2) * N_ + m];  // symmetry: col m pattern = row m
    }
    int tot = cnt;
    if (g_adiag[mrow] == 0.f) {
        if (tid == 0) { sn[cnt] = m; sv[cnt] = S_out[mrow * N_ + m]; }
        tot = cnt + 1;
    }
    __syncthreads();
    for (int j = tid; j < A; j += 256) {
        float acc = 0.f;
        for (int e = 0; e < tot; e++)
            acc += sv[e] * g_T[((size_t)b * N_ + sn[e]) * ACAP + j];
        float c = floorf(acc * 10000.0f) / 10000.0f;
        int l = g_colid[b * ACAP + j];
        out_co[((size_t)b * N_ + m) * N_ + l] = c;
    }
}

// ---- K9: x_c active rows = Scol_m^T . x ----
__global__ void k_xc(const float* __restrict__ x, const float* __restrict__ S_out,
                     float* __restrict__ out_xc){
    int b = blockIdx.y;
    int jm = blockIdx.x;
    int A = g_acnt[b];
    if (jm >= A) return;
    int tid = threadIdx.x;   // = feature index (F_=256)
    int m = g_colid[b * ACAP + jm];
    size_t mrow = (size_t)b * N_ + m;
    __shared__ int   sn[CSRCAP + 1];
    __shared__ float sv[CSRCAP + 1];
    int cnt = g_ccnt[mrow], base = (int)mrow * CSRCAP;
    if (tid < cnt) {
        int n2 = g_ccol[base + tid];
        sn[tid] = n2;
        sv[tid] = S_out[((size_t)b * N_ + n2) * N_ + m];
    }
    int tot = cnt;
    if (g_adiag[mrow] == 0.f) {
        if (tid == 0) { sn[cnt] = m; sv[cnt] = S_out[mrow * N_ + m]; }
        tot = cnt + 1;
    }
    __syncthreads();
    float acc = 0.f;
    for (int e = 0; e < tot; e++)
        acc += sv[e] * x[((size_t)b * N_ + sn[e]) * F_ + tid];
    out_xc[((size_t)b * N_ + m) * F_ + tid] = acc;
}

extern "C" void kernel_launch(void* const* d_in, const int* in_sizes, int n_in,
                              void* d_out, int out_size) {
    const float* x   = (const float*)d_in[0];
    const float* adj = (const float*)d_in[1];
    const float* W   = (const float*)d_in[2];
    const float* bb  = (const float*)d_in[3];
    float* out = (float*)d_out;

    const size_t XC = 0;
    const size_t CO = (size_t)B_ * N_ * F_;
    const size_t SO = CO + (size_t)B_ * N_ * N_;
    const size_t TI = SO + (size_t)B_ * N_ * N_;

    cudaMemsetAsync(d_out, 0, (size_t)out_size * sizeof(float), 0);

    k_csr  <<<ROWS_ / 8, 256>>>(adj);
    k_t    <<<ROWS_ / 8, 256>>>(x, W);
    k_dg   <<<(ROWS_ + 255) / 256, 256>>>();
    k_alpha<<<ROWS_ / 8, 256>>>(bb);
    k_topk <<<B_, 1024>>>(out + TI);
    k_sbuild<<<ROWS_ / 8, 256>>>(out + SO);
    k_T    <<<ROWS_, 128>>>();
    dim3 gblk(ACAP, B_);
    k_coarse<<<gblk, 256>>>(out + SO, out + CO);
    k_xc    <<<gblk, 256>>>(x, out + SO, out + XC);
}

// round 4
// speedup vs baseline: 1.1382x; 1.1382x over previous
#include <cuda_runtime.h>
#include <math.h>

#define B_ 8
#define N_ 2048
#define F_ 256
#define K_ 205
#define ACAP 256
#define CSRCAP 128
#define SROWCAP 130
#define ROWS_ (B_*N_)
#define ZBLK 8192

// ---- static scratch (no runtime allocation allowed) ----
__device__ float g_t[ROWS_];
__device__ float g_radj[ROWS_];
__device__ float g_adiag[ROWS_];
__device__ float g_dg[ROWS_];
__device__ float g_alpha[ROWS_];
__device__ int   g_ccol[ROWS_*CSRCAP];
__device__ float g_cval[ROWS_*CSRCAP];
__device__ int   g_ccnt[ROWS_];
__device__ int   g_sj[ROWS_*SROWCAP];
__device__ float g_sv[ROWS_*SROWCAP];
__device__ int   g_scnt[ROWS_];
__device__ int   g_colid[B_*ACAP];
__device__ float g_w[B_*ACAP];
__device__ int   g_acnt[B_];
__device__ int   g_rank[ROWS_];
__device__ float g_T[(size_t)ROWS_*ACAP];

// ---- KA: fused {CSR+rowsum+diag+dg} | {t = x@W} | {zero entire output} ----
__global__ void kA(const float* __restrict__ adj, const float* __restrict__ x,
                   const float* __restrict__ W, float* __restrict__ out,
                   size_t out_elems){
    int blk = blockIdx.x;
    int lane = threadIdx.x & 31;
    if (blk < 2048) {
        // CSR of adj, one warp per row (order-preserving compaction) + dg
        int row = blk * 8 + (threadIdx.x >> 5);
        int n = row % N_;
        const float* ar = adj + (size_t)row * N_;
        float sum = 0.f, diag = 0.f;
        int cnt = 0, base = row * CSRCAP;
        for (int c = 0; c < N_; c += 32) {
            int m = c + lane;
            float a = ar[m];
            sum += a;
            if (m == n) diag = a;
            unsigned msk = __ballot_sync(0xffffffffu, a != 0.f);
            if (a != 0.f) {
                int pos = cnt + __popc(msk & ((1u << lane) - 1u));
                if (pos < CSRCAP) { g_ccol[base + pos] = m; g_cval[base + pos] = a; }
            }
            cnt += __popc(msk);
        }
        #pragma unroll
        for (int o = 16; o; o >>= 1) {
            sum  += __shfl_xor_sync(0xffffffffu, sum,  o);
            diag += __shfl_xor_sync(0xffffffffu, diag, o);
        }
        if (lane == 0) {
            g_radj[row] = sum;
            g_adiag[row] = diag;
            g_ccnt[row] = cnt < CSRCAP ? cnt : CSRCAP;
            g_dg[row] = rsqrtf(sum + 1.f);
        }
    } else if (blk < 4096) {
        // t = x @ W, one warp per row
        int row = (blk - 2048) * 8 + (threadIdx.x >> 5);
        const float* xr = x + (size_t)row * F_;
        float s = 0.f;
        #pragma unroll
        for (int f = lane; f < F_; f += 32) s += xr[f] * W[f];
        #pragma unroll
        for (int o = 16; o; o >>= 1) s += __shfl_xor_sync(0xffffffffu, s, o);
        if (lane == 0) g_t[row] = s;
    } else {
        // zero the whole output (out_elems divisible by 4; d_out 256B aligned)
        size_t i = (size_t)(blk - 4096) * blockDim.x + threadIdx.x;
        size_t tot4 = out_elems >> 2;
        float4 z = make_float4(0.f, 0.f, 0.f, 0.f);
        float4* o4 = (float4*)out;
        size_t stride = (size_t)ZBLK * blockDim.x;
        for (; i < tot4; i += stride) o4[i] = z;
    }
}

// ---- KB: alpha = sigmoid((dg_n * (sum_m A_hat[n,m] dg_m t_m) + b)^2) ----
__global__ void k_alpha(const float* __restrict__ bptr){
    int row = blockIdx.x * 8 + (threadIdx.x >> 5);
    if (row >= ROWS_) return;
    int lane = threadIdx.x & 31;
    int bN = (row / N_) * N_;
    int base = row * CSRCAP;
    int cnt = g_ccnt[row];
    float s = 0.f;
    for (int e = lane; e < cnt; e += 32) {
        int m = g_ccol[base + e];
        s += g_cval[base + e] * __ldg(&g_dg[bN + m]) * __ldg(&g_t[bN + m]);
    }
    #pragma unroll
    for (int o = 16; o; o >>= 1) s += __shfl_xor_sync(0xffffffffu, s, o);
    if (lane == 0) {
        s += g_dg[row] * g_t[row];            // identity part of A_hat
        float pre = g_dg[row] * s + bptr[0];
        float z = pre * pre;
        g_alpha[row] = 1.f / (1.f + expf(-z));
    }
}

// ---- KC: per-batch top-K via bitonic sort of 2048 (value desc, index asc) ----
__global__ void k_topk(float* __restrict__ out_ti){
    int b = blockIdx.x;
    int tid = threadIdx.x;
    __shared__ unsigned long long sk[N_];
    __shared__ float cutv;
    __shared__ int acnt;
    for (int i = tid; i < N_; i += 1024) {
        g_rank[b * N_ + i] = -1;
        float v = g_alpha[b * N_ + i];
        unsigned u = __float_as_uint(v);
        u = (u & 0x80000000u) ? ~u : (u | 0x80000000u);   // orderable
        sk[i] = ((unsigned long long)(~u) << 32) | (unsigned)i; // asc key = desc value
    }
    __syncthreads();
    for (int k = 2; k <= N_; k <<= 1) {
        for (int j = k >> 1; j > 0; j >>= 1) {
            for (int t = tid; t < N_; t += 1024) {
                int ixj = t ^ j;
                if (ixj > t) {
                    bool up = ((t & k) == 0);
                    unsigned long long a = sk[t], c = sk[ixj];
                    if ((a > c) == up) { sk[t] = c; sk[ixj] = a; }
                }
            }
            __syncthreads();
        }
    }
    if (tid == 0) {
        int idxK = (int)(sk[K_ - 1] & 0xffffffffu);
        cutv = g_alpha[b * N_ + idxK];
        int A = K_;
        while (A < ACAP) {      // near-ties within 1e-7 below cut also get weight
            int id = (int)(sk[A] & 0xffffffffu);
            float v = g_alpha[b * N_ + id];
            if (v + 1e-7f - cutv > 0.f) A++; else break;
        }
        acnt = A;
        g_acnt[b] = A;
    }
    __syncthreads();
    for (int j = tid; j < acnt; j += 1024) {
        int id = (int)(sk[j] & 0xffffffffu);
        g_colid[b * ACAP + j] = id;
        g_w[b * ACAP + j] = g_alpha[b * N_ + id] + 1e-7f - cutv;
        g_rank[b * N_ + id] = j;
    }
    for (int j = tid; j < K_; j += 1024) {
        int id = (int)(sk[j] & 0xffffffffu);
        out_ti[b * K_ + j] = (float)id;
    }
}

// ---- KD: build normalized S rows (sparse list + dense scatter into zeroed S) ----
__global__ void k_sbuild(float* __restrict__ S_out){
    int row = blockIdx.x * 8 + (threadIdx.x >> 5);
    if (row >= ROWS_) return;
    int lane = threadIdx.x & 31;
    int b = row / N_, n = row % N_;
    if (g_radj[row] <= 0.f) {                 // mask = (adj.sum(-1) > 0)
        if (lane == 0) g_scnt[row] = 0;
        return;
    }
    float dgn = g_dg[row];
    int cnt = g_ccnt[row], base = row * CSRCAP;
    bool hasdiag = (g_adiag[row] != 0.f);
    // pass 1: row sum of unnormalized S
    float rs = 0.f;
    for (int e = lane; e < cnt; e += 32) {
        int m = g_ccol[base + e];
        int j = g_rank[b * N_ + m];
        if (j >= 0) {
            float ahat = g_cval[base + e] + (m == n ? 1.f : 0.f);
            rs += dgn * ahat * g_dg[b * N_ + m] * g_w[b * ACAP + j];
        }
    }
    if (!hasdiag && lane == 0) {
        int j = g_rank[row];
        if (j >= 0) rs += dgn * dgn * g_w[b * ACAP + j];
    }
    #pragma unroll
    for (int o = 16; o; o >>= 1) rs += __shfl_xor_sync(0xffffffffu, rs, o);
    float inv = 1.f / fmaxf(rs, 1e-12f);
    // pass 2: write normalized values (order-preserving)
    int sc = 0, sbase = row * SROWCAP;
    for (int c = 0; c < cnt; c += 32) {
        int e = c + lane;
        bool act = false; int j = -1, m = -1; float v = 0.f;
        if (e < cnt) {
            m = g_ccol[base + e];
            j = g_rank[b * N_ + m];
            if (j >= 0) {
                act = true;
                float ahat = g_cval[base + e] + (m == n ? 1.f : 0.f);
                v = dgn * ahat * g_dg[b * N_ + m] * g_w[b * ACAP + j] * inv;
            }
        }
        unsigned msk = __ballot_sync(0xffffffffu, act);
        if (act) {
            int pos = sc + __popc(msk & ((1u << lane) - 1u));
            if (pos < SROWCAP) { g_sj[sbase + pos] = j; g_sv[sbase + pos] = v; }
            S_out[(size_t)row * N_ + m] = v;
        }
        sc += __popc(msk);
    }
    if (!hasdiag) {
        int add = 0;
        if (lane == 0) {
            int j = g_rank[row];
            if (j >= 0) {
                float v = dgn * dgn * g_w[b * ACAP + j] * inv;
                if (sc < SROWCAP) { g_sj[sbase + sc] = j; g_sv[sbase + sc] = v; }
                S_out[(size_t)row * N_ + n] = v;
                add = 1;
            }
        }
        sc += __shfl_sync(0xffffffffu, add, 0);
    }
    if (lane == 0) g_scnt[row] = sc < SROWCAP ? sc : SROWCAP;
}

// ---- KE: T[n,:] = sum_k adj[n,k] * Srow[k]  (warp per row, smem accumulators) ----
__global__ void k_T(){
    int w = threadIdx.x >> 5;
    int row = blockIdx.x * 8 + w;
    int lane = threadIdx.x & 31;
    __shared__ float acc[8][ACAP];
    float* a = acc[w];
    for (int i = lane; i < ACAP; i += 32) a[i] = 0.f;
    __syncwarp();
    int b = row / N_;
    int cnt = g_ccnt[row], base = row * CSRCAP;
    for (int e = lane; e < cnt; e += 32) {
        int k = g_ccol[base + e];
        float av = g_cval[base + e];
        size_t krow = (size_t)b * N_ + k;
        int sb = (int)krow * SROWCAP;
        int sc = g_scnt[krow];
        for (int q = 0; q < sc; q++)
            atomicAdd(&a[g_sj[sb + q]], av * g_sv[sb + q]);
    }
    __syncwarp();
    int A = g_acnt[b];
    float* Trow = g_T + (size_t)row * ACAP;
    for (int j = lane; j < A; j += 32) Trow[j] = a[j];
}

// ---- KF: fused coarse + x_c for each active column m ----
__global__ void k_cx(const float* __restrict__ x, const float* __restrict__ S_out,
                     float* __restrict__ out_co, float* __restrict__ out_xc){
    int b = blockIdx.y;
    int jm = blockIdx.x;
    int A = g_acnt[b];
    if (jm >= A) return;
    int tid = threadIdx.x;
    int m = g_colid[b * ACAP + jm];
    size_t mrow = (size_t)b * N_ + m;
    __shared__ int   sn[CSRCAP + 1];
    __shared__ float sv[CSRCAP + 1];
    int cnt = g_ccnt[mrow], base = (int)mrow * CSRCAP;
    if (tid < cnt) {
        int n2 = g_ccol[base + tid];
        sn[tid] = n2;
        sv[tid] = S_out[((size_t)b * N_ + n2) * N_ + m];  // symmetry: col m pattern = row m
    }
    int tot = cnt;
    if (g_adiag[mrow] == 0.f) {
        if (tid == 0) { sn[cnt] = m; sv[cnt] = S_out[mrow * N_ + m]; }
        tot = cnt + 1;
    }
    __syncthreads();
    // x_c: tid = feature index (F_ == blockDim.x == 256)
    {
        float acc = 0.f;
        for (int e = 0; e < tot; e++)
            acc += sv[e] * x[((size_t)b * N_ + sn[e]) * F_ + tid];
        out_xc[mrow * F_ + tid] = acc;
    }
    // coarse: active block column jm, all active rows j
    for (int j = tid; j < A; j += 256) {
        float acc = 0.f;
        for (int e = 0; e < tot; e++)
            acc += sv[e] * g_T[((size_t)b * N_ + sn[e]) * ACAP + j];
        float c = floorf(acc * 10000.0f) / 10000.0f;
        int l = g_colid[b * ACAP + j];
        out_co[mrow * N_ + l] = c;
    }
}

extern "C" void kernel_launch(void* const* d_in, const int* in_sizes, int n_in,
                              void* d_out, int out_size) {
    const float* x   = (const float*)d_in[0];
    const float* adj = (const float*)d_in[1];
    const float* W   = (const float*)d_in[2];
    const float* bb  = (const float*)d_in[3];
    float* out = (float*)d_out;

    const size_t XC = 0;
    const size_t CO = (size_t)B_ * N_ * F_;
    const size_t SO = CO + (size_t)B_ * N_ * N_;
    const size_t TI = SO + (size_t)B_ * N_ * N_;

    kA      <<<4096 + ZBLK, 256>>>(adj, x, W, out, (size_t)out_size);
    k_alpha <<<ROWS_ / 8, 256>>>(bb);
    k_topk  <<<B_, 1024>>>(out + TI);
    k_sbuild<<<ROWS_ / 8, 256>>>(out + SO);
    k_T     <<<ROWS_ / 8, 256>>>();
    dim3 gblk(ACAP, B_);
    k_cx    <<<gblk, 256>>>(x, out + SO, out + CO, out + XC);
}